// round 2
// baseline (speedup 1.0000x reference)
#include <cuda_runtime.h>
#include <math.h>

#define L_ 128
#define N_ 8
#define S_ 16384
#define C_ 256

// ---------------- device scratch (no allocations allowed) -------------------
__device__ float g_qproj[N_ * L_ * C_];              // [n][l][j]
__device__ unsigned long long g_best[N_ * L_];       // packed (key<<32)|(~s)

typedef unsigned long long ull;

__device__ __forceinline__ ull pk2(float a, float b) {
    ull r; asm("mov.b64 %0, {%1, %2};" : "=l"(r) : "f"(a), "f"(b)); return r;
}
__device__ __forceinline__ void up2(ull v, float &a, float &b) {
    asm("mov.b64 {%0, %1}, %2;" : "=f"(a), "=f"(b) : "l"(v));
}
// packed fp32 FMA (Blackwell FFMA2): d.lo += a.lo*b.lo ; d.hi += a.hi*b.hi
#define FMA2(d, a, b) asm("fma.rn.f32x2 %0, %1, %2, %0;" : "+l"(d) : "l"(a), "l"(b))

// ---------------- shared memory layout (floats) -----------------------------
#define AS_STRIDE 33
#define BS_STRIDE 258
#define KT_STRIDE 132
#define QS_STRIDE 260
#define AS_OFF 0                       // phase 1 A tile   128 x AS_STRIDE
#define BS_OFF (128 * AS_STRIDE)       // phase 1 W tile    32 x BS_STRIDE
#define QS_OFF 0                       // phase 2 q tile    64 x QS_STRIDE (aliases As/Bs)
#define KT_OFF 16640                   // kpT              256 x KT_STRIDE
#define RSQ_OFF (KT_OFF + 256 * KT_STRIDE)     // 128 floats
#define SMEM_FLOATS (RSQ_OFF + 128)            // 50560
#define SMEM_BYTES (SMEM_FLOATS * 4)           // 202240

__device__ __forceinline__ unsigned fkey(float f) {
    unsigned u = __float_as_uint(f);
    return (u & 0x80000000u) ? ~u : (u | 0x80000000u);
}

__global__ void initKernel() {
    g_best[threadIdx.x] = 0ull;   // smaller than any real packed key
}

// ============================================================================
// fusedKernel
//   mode 0 (grid 8x1):    q_proj[n][l][:] = (A1+A2) @ W^T + bias   -> g_qproj
//   mode 1 (grid 128x8):  kp = (A1+A2)@W^T+bias for 128 s-rows of batch n;
//                         logits vs q_proj[n]; fused argmax -> g_best
// ============================================================================
__global__ void __launch_bounds__(256, 1)
fusedKernel(const float* __restrict__ A1, const float* __restrict__ A2,
            const float* __restrict__ W,  const float* __restrict__ bias,
            int kmode) {
    extern __shared__ float sm[];
    float* As  = sm + AS_OFF;
    float* Bs  = sm + BS_OFF;
    float* ksT = sm + KT_OFF;
    float* rsq = sm + RSQ_OFF;

    const int tid = threadIdx.x;
    const int tj = tid & 15;        // col group (16 groups x 16 cols)
    const int ts = tid >> 4;        // row group (16 groups x 8 rows)
    const int lr = tid >> 1, lh = tid & 1;
    const int n = blockIdx.y;
    const int row0 = blockIdx.x * 128;

    // -------- phase 1: GEMM1, thread tile 8 rows x 16 cols (8 f32x2 pairs) --
    ull acc[8][8];
#pragma unroll
    for (int k = 0; k < 8; k++) {
        int j = 32 * k + tj * 2;
        ull bb = pk2(bias[j], bias[j + 1]);
#pragma unroll
        for (int r = 0; r < 8; r++) acc[r][k] = bb;
    }

    for (int kc = 0; kc < C_; kc += 32) {
        {   // stage A rows (fused add), 128 x 32
            int g = kmode ? (((row0 + lr) * N_ + n) * C_ + kc + lh * 16)
                          : ((row0 + lr) * C_ + kc + lh * 16);
            const float4* p1 = (const float4*)(A1 + g);
            const float4* p2 = (const float4*)(A2 + g);
            float* dst = As + lr * AS_STRIDE + lh * 16;
#pragma unroll
            for (int i = 0; i < 4; i++) {
                float4 a = p1[i], b = p2[i];
                dst[i * 4 + 0] = a.x + b.x; dst[i * 4 + 1] = a.y + b.y;
                dst[i * 4 + 2] = a.z + b.z; dst[i * 4 + 3] = a.w + b.w;
            }
        }
#pragma unroll
        for (int it = 0; it < 2; it++) {  // stage W chunk transposed: Bs[c][j]
            int j = lr + it * 128;
            const float4* pw = (const float4*)(W + j * C_ + kc + lh * 16);
#pragma unroll
            for (int i = 0; i < 4; i++) {
                float4 w = pw[i];
                int c = lh * 16 + i * 4;
                Bs[(c + 0) * BS_STRIDE + j] = w.x;
                Bs[(c + 1) * BS_STRIDE + j] = w.y;
                Bs[(c + 2) * BS_STRIDE + j] = w.z;
                Bs[(c + 3) * BS_STRIDE + j] = w.w;
            }
        }
        __syncthreads();
#pragma unroll 4
        for (int c = 0; c < 32; c++) {
            ull a2[8], b2[8];
#pragma unroll
            for (int r = 0; r < 8; r++) {
                float av = As[(ts * 8 + r) * AS_STRIDE + c];
                a2[r] = pk2(av, av);
            }
#pragma unroll
            for (int k = 0; k < 8; k++)
                b2[k] = *(const ull*)(Bs + c * BS_STRIDE + 32 * k + tj * 2);
#pragma unroll
            for (int r = 0; r < 8; r++)
#pragma unroll
                for (int k = 0; k < 8; k++) FMA2(acc[r][k], a2[r], b2[k]);
        }
        __syncthreads();
    }

    if (!kmode) {   // write q_proj to [n][l][j] layout
#pragma unroll
        for (int r = 0; r < 8; r++) {
            int g = row0 + ts * 8 + r;
            int l2 = g >> 3, n2 = g & 7;
            float* o = g_qproj + (n2 * L_ + l2) * C_;
#pragma unroll
            for (int k = 0; k < 8; k++)
                *(ull*)(o + 32 * k + tj * 2) = acc[r][k];
        }
        return;
    }

    // -------- store kp transposed: ksT[j][s_local] ---------------------------
#pragma unroll
    for (int r = 0; r < 8; r++) {
        int srow = ts * 8 + r;
#pragma unroll
        for (int k = 0; k < 8; k++) {
            float f0, f1; up2(acc[r][k], f0, f1);
            int j = 32 * k + tj * 2;
            ksT[j * KT_STRIDE + srow] = f0;
            ksT[(j + 1) * KT_STRIDE + srow] = f1;
        }
    }
    __syncthreads();

    // -------- row norms: rsq[s] = 1 / max(||kp_s||, 1e-12) -------------------
    if (tid < 128) {
        float ss = 0.f;
#pragma unroll 8
        for (int c = 0; c < C_; c++) {
            float v = ksT[c * KT_STRIDE + tid];
            ss = fmaf(v, v, ss);
        }
        rsq[tid] = 1.0f / fmaxf(sqrtf(ss), 1e-12f);
    }
    __syncthreads();

    // -------- phase 2: logits (q_proj . kp) * rsq, fused argmax --------------
    const int sg = tid & 31;        // s group: 4 s each
    const int lg = tid >> 5;        // l group (== warp): 8 l each
    float* qs = sm + QS_OFF;

    for (int lt = 0; lt < 2; lt++) {            // two 64-row q tiles
        for (int idx = tid; idx < 64 * 64; idx += 256) {
            int row = idx >> 6, c4 = idx & 63;
            float4 v = *(const float4*)(g_qproj + (n * L_ + lt * 64 + row) * C_ + c4 * 4);
            *(float4*)(qs + row * QS_STRIDE + c4 * 4) = v;
        }
        __syncthreads();

        ull a2[8][4];
#pragma unroll
        for (int r = 0; r < 8; r++)
#pragma unroll
            for (int i = 0; i < 4; i++) a2[r][i] = 0ull;

#pragma unroll 2
        for (int c = 0; c < C_; c += 2) {
            float4 k0 = *(const float4*)(ksT + c * KT_STRIDE + sg * 4);
            float4 k1 = *(const float4*)(ksT + (c + 1) * KT_STRIDE + sg * 4);
            ull kp[4];
            kp[0] = pk2(k0.x, k1.x); kp[1] = pk2(k0.y, k1.y);
            kp[2] = pk2(k0.z, k1.z); kp[3] = pk2(k0.w, k1.w);
#pragma unroll
            for (int r = 0; r < 8; r++) {
                ull q2 = *(const ull*)(qs + (lg * 8 + r) * QS_STRIDE + c);
#pragma unroll
                for (int i = 0; i < 4; i++) FMA2(a2[r][i], q2, kp[i]);
            }
        }

        // per-thread best over its 4 s, then warp reduce over the 32 sg
#pragma unroll
        for (int r = 0; r < 8; r++) {
            float bv = -1e30f; int bs = 0;
#pragma unroll
            for (int i = 0; i < 4; i++) {
                float x, y; up2(a2[r][i], x, y);
                float val = (x + y) * rsq[sg * 4 + i];
                if (val > bv) { bv = val; bs = sg * 4 + i; }
            }
            ull pk = ((ull)fkey(bv) << 32) | (ull)(0xFFFFFFFFu - (unsigned)(row0 + bs));
#pragma unroll
            for (int m = 16; m >= 1; m >>= 1) {
                ull o = __shfl_xor_sync(0xFFFFFFFFu, pk, m);
                if (o > pk) pk = o;
            }
            if (sg == 0) {
                int lglob = lt * 64 + lg * 8 + r;
                atomicMax(&g_best[n * L_ + lglob], pk);
            }
        }
        __syncthreads();
    }
}

// ============================================================================
// finalKernel: per block, 8 winners (same n): recompute kp(s*), v, upd,
// residual + LayerNorm. 128 blocks x 256 threads.
// ============================================================================
__device__ __forceinline__ void gemv8(const float* in, float* out_,
                                      const float* __restrict__ W,
                                      const float* __restrict__ bias, int j) {
    float acc[8];
#pragma unroll
    for (int r = 0; r < 8; r++) acc[r] = bias[j];
    const float4* w4 = (const float4*)(W + j * C_);
#pragma unroll 4
    for (int c4 = 0; c4 < 64; c4++) {
        float4 w = w4[c4];
#pragma unroll
        for (int r = 0; r < 8; r++) {
            float4 a = ((const float4*)(in + r * 260))[c4];
            acc[r] = fmaf(a.x, w.x, fmaf(a.y, w.y, fmaf(a.z, w.z, fmaf(a.w, w.w, acc[r]))));
        }
    }
#pragma unroll
    for (int r = 0; r < 8; r++) out_[r * 260 + j] = acc[r];
}

__global__ void __launch_bounds__(256)
finalKernel(const float* __restrict__ tgt, const float* __restrict__ memory,
            const float* __restrict__ pos,
            const float* __restrict__ Wp, const float* __restrict__ bp,
            const float* __restrict__ Wv, const float* __restrict__ bv,
            const float* __restrict__ Wo, const float* __restrict__ bo,
            const float* __restrict__ gamma, const float* __restrict__ beta,
            float* __restrict__ out) {
    __shared__ float bufA[8 * 260];
    __shared__ float bufB[8 * 260];
    __shared__ unsigned sidx[8];

    const int tid = threadIdx.x;
    const int b = blockIdx.x;
    const int n = b >> 4;                 // constant per block

    if (tid < 8) {
        ull pk = g_best[b * 8 + tid];
        sidx[tid] = 0xFFFFFFFFu - (unsigned)(pk & 0xFFFFFFFFu);
    }
    __syncthreads();

    // load winner k rows (memory+pos)
    for (int idx = tid; idx < 8 * 256; idx += 256) {
        int r = idx >> 8, j = idx & 255;
        int s = (int)sidx[r];
        int g = (s * N_ + n) * C_ + j;
        bufA[r * 260 + j] = memory[g] + pos[g];
    }
    __syncthreads();

    gemv8(bufA, bufB, Wp, bp, tid);       // kp
    __syncthreads();
    gemv8(bufB, bufA, Wv, bv, tid);       // v
    __syncthreads();
    gemv8(bufA, bufB, Wo, bo, tid);       // upd
    __syncthreads();

    // residual: x = tgt + upd
#pragma unroll
    for (int r = 0; r < 8; r++) {
        int l = (b & 15) * 8 + r;
        bufB[r * 260 + tid] += tgt[(l * N_ + n) * C_ + tid];
    }
    __syncthreads();

    // LayerNorm: warp w handles row w
    const int w = tid >> 5, lane = tid & 31;
    float s1 = 0.f, s2 = 0.f;
#pragma unroll
    for (int k = 0; k < 8; k++) {
        float v = bufB[w * 260 + lane + k * 32];
        s1 += v;
        s2 = fmaf(v, v, s2);
    }
#pragma unroll
    for (int m = 16; m >= 1; m >>= 1) {
        s1 += __shfl_xor_sync(0xFFFFFFFFu, s1, m);
        s2 += __shfl_xor_sync(0xFFFFFFFFu, s2, m);
    }
    float mu = s1 * (1.0f / 256.0f);
    float var = s2 * (1.0f / 256.0f) - mu * mu;
    float rstd = rsqrtf(var + 1e-5f);

    int l = (b & 15) * 8 + w;
    float* o = out + (l * N_ + n) * C_;
#pragma unroll
    for (int k = 0; k < 8; k++) {
        int j = lane + k * 32;
        float v = bufB[w * 260 + j];
        o[j] = (v - mu) * rstd * gamma[j] + beta[j];
    }
}

// ============================================================================
extern "C" void kernel_launch(void* const* d_in, const int* in_sizes, int n_in,
                              void* d_out, int out_size) {
    const float* tgt    = (const float*)d_in[0];
    const float* memory = (const float*)d_in[1];
    const float* pos    = (const float*)d_in[2];
    const float* qpos   = (const float*)d_in[3];
    const float* Wq     = (const float*)d_in[4];
    const float* bq     = (const float*)d_in[5];
    const float* Wp     = (const float*)d_in[6];
    const float* bp     = (const float*)d_in[7];
    const float* Wv     = (const float*)d_in[8];
    const float* bv     = (const float*)d_in[9];
    const float* Wo     = (const float*)d_in[10];
    const float* bo     = (const float*)d_in[11];
    const float* gamma  = (const float*)d_in[12];
    const float* beta   = (const float*)d_in[13];
    float* out = (float*)d_out;

    cudaFuncSetAttribute(fusedKernel, cudaFuncAttributeMaxDynamicSharedMemorySize,
                         SMEM_BYTES);

    initKernel<<<1, N_ * L_>>>();
    fusedKernel<<<dim3(8, 1), 256, SMEM_BYTES>>>(tgt, qpos, Wq, bq, 0);
    fusedKernel<<<dim3(S_ / 128, N_), 256, SMEM_BYTES>>>(memory, pos, Wp, bp, 1);
    finalKernel<<<128, 256>>>(tgt, memory, pos, Wp, bp, Wv, bv, Wo, bo,
                              gamma, beta, out);
}

// round 6
// speedup vs baseline: 1.9876x; 1.9876x over previous
#include <cuda_runtime.h>
#include <cstdint>
#include <math.h>

#define L_ 128
#define N_ 8
#define S_ 16384
#define C_ 256
#define MARGIN 0.15f
#define CAND_CAP (1 << 20)
#define SURV_CAP (1 << 18)

typedef unsigned long long ull;
typedef unsigned int u32;

// ---------------- device scratch (no allocations allowed) -------------------
__device__ float g_qproj[N_ * L_ * C_];          // exact fp32 q_proj [n][l][c]
__device__ u32   g_qB[N_ * L_ * C_ / 2];         // bf16x2 Q, [n][l][c/2]
__device__ u32   g_WpB[C_ * C_ / 2];             // bf16x2 Wp, [half][j][c/2]
__device__ float g_WpT[C_ * C_];                 // fp32 transposed weights [c][j]
__device__ float g_WvT[C_ * C_];
__device__ float g_WoT[C_ * C_];
__device__ ull   g_bestA[N_ * L_];               // approx packed max
__device__ ull   g_bestE[N_ * L_];               // exact packed max
__device__ int   g_ncand, g_nsurv;
__device__ uint4 g_cand[CAND_CAP];               // {n, l, s, approx_bits}
__device__ uint4 g_surv[SURV_CAP];

// ---------------- small helpers --------------------------------------------
__device__ __forceinline__ ull pk2(float a, float b) {
    ull r; asm("mov.b64 %0, {%1, %2};" : "=l"(r) : "f"(a), "f"(b)); return r;
}
__device__ __forceinline__ void up2(ull v, float &a, float &b) {
    asm("mov.b64 {%0, %1}, %2;" : "=f"(a), "=f"(b) : "l"(v));
}
#define FMA2(d, a, b) asm("fma.rn.f32x2 %0, %1, %2, %0;" : "+l"(d) : "l"(a), "l"(b))

__device__ __forceinline__ u32 fkey(float f) {
    u32 u = __float_as_uint(f);
    return (u & 0x80000000u) ? ~u : (u | 0x80000000u);
}
__device__ __forceinline__ float unfkey(u32 k) {
    return (k & 0x80000000u) ? __uint_as_float(k & 0x7FFFFFFFu)
                             : __uint_as_float(~k);
}
__device__ __forceinline__ u32 bfp(float lo, float hi) {   // bf16x2 {hi|lo}
    u32 r; asm("cvt.rn.bf16x2.f32 %0, %1, %2;" : "=r"(r) : "f"(hi), "f"(lo));
    return r;
}

// mma.sync m16n8k16 row.col bf16 -> f32 accum
#define MMA16816(c, a0, a1, a2, a3, b0, b1) \
    asm volatile("mma.sync.aligned.m16n8k16.row.col.f32.bf16.bf16.f32 " \
        "{%0,%1,%2,%3}, {%4,%5,%6,%7}, {%8,%9}, {%0,%1,%2,%3};" \
        : "+f"((c)[0]), "+f"((c)[1]), "+f"((c)[2]), "+f"((c)[3]) \
        : "r"(a0), "r"(a1), "r"(a2), "r"(a3), "r"(b0), "r"(b1))

// ---------------- init ------------------------------------------------------
__global__ void initKernel() {
    int t = threadIdx.x;
    g_bestA[t] = 0ull;
    g_bestE[t] = 0ull;
    if (t == 0) { g_ncand = 0; g_nsurv = 0; }
}

// ---------------- weight prep: transposes + bf16 Wp -------------------------
__global__ void __launch_bounds__(256)
convWKernel(const float* __restrict__ Wp, const float* __restrict__ Wv,
            const float* __restrict__ Wo) {
    int j = blockIdx.x;
    int c = threadIdx.x;
    float wp = Wp[j * C_ + c];
    g_WpT[c * C_ + j] = wp;
    g_WvT[c * C_ + j] = Wv[j * C_ + c];
    g_WoT[c * C_ + j] = Wo[j * C_ + c];
    if ((c & 1) == 0) {
        float wp1 = Wp[j * C_ + c + 1];
        int half = j >> 7, jr = j & 127;
        g_WpB[half * 16384 + jr * 128 + (c >> 1)] = bfp(wp, wp1);
    }
}

// ---------------- exact fp32 q_proj (FFMA2), 64 blocks x 16 rows ------------
__global__ void __launch_bounds__(256)
qprojKernel(const float* __restrict__ tgt, const float* __restrict__ qpos,
            const float* __restrict__ Wq, const float* __restrict__ bq) {
    __shared__ float As[16 * 33];
    __shared__ float Bs[32 * 258];
    const int tid = threadIdx.x;
    const int tj = tid & 15;
    const int ts = tid >> 4;
    const int row0 = blockIdx.x * 16;

    ull acc[8];
#pragma unroll
    for (int k = 0; k < 8; k++) {
        int j = 32 * k + tj * 2;
        acc[k] = pk2(bq[j], bq[j + 1]);
    }

    for (int kc = 0; kc < C_; kc += 32) {
        if (tid < 128) {
            int lr = tid >> 3, c4 = (tid & 7) * 4;
            int g = (row0 + lr) * C_ + kc + c4;
            float4 a = *(const float4*)(tgt + g);
            float4 b = *(const float4*)(qpos + g);
            float* d = As + lr * 33 + c4;
            d[0] = a.x + b.x; d[1] = a.y + b.y; d[2] = a.z + b.z; d[3] = a.w + b.w;
        }
        {
            int lr = tid >> 1, lh = tid & 1;
#pragma unroll
            for (int it = 0; it < 2; it++) {
                int j = lr + it * 128;
                const float4* pw = (const float4*)(Wq + j * C_ + kc + lh * 16);
#pragma unroll
                for (int i = 0; i < 4; i++) {
                    float4 w = pw[i];
                    int c = lh * 16 + i * 4;
                    Bs[(c + 0) * 258 + j] = w.x;
                    Bs[(c + 1) * 258 + j] = w.y;
                    Bs[(c + 2) * 258 + j] = w.z;
                    Bs[(c + 3) * 258 + j] = w.w;
                }
            }
        }
        __syncthreads();
#pragma unroll 4
        for (int c = 0; c < 32; c++) {
            float av = As[ts * 33 + c];
            ull a2 = pk2(av, av);
#pragma unroll
            for (int k = 0; k < 8; k++) {
                ull b2 = *(const ull*)(Bs + c * 258 + 32 * k + tj * 2);
                FMA2(acc[k], a2, b2);
            }
        }
        __syncthreads();
    }

    int row = row0 + ts;
    int l = row >> 3, n = row & 7;
    float* of = g_qproj + (n * L_ + l) * C_;
#pragma unroll
    for (int k = 0; k < 8; k++) {
        int j = 32 * k + tj * 2;
        *(ull*)(of + j) = acc[k];
        float f0, f1; up2(acc[k], f0, f1);
        g_qB[n * 16384 + l * 128 + (j >> 1)] = bfp(f0, f1);
    }
}

// ---------------- fused mma.sync kernel -------------------------------------
#define STRW 132                          // u32 words per smem row
#define AB_OFF 0
#define WB_OFF (128 * STRW)               // 16896
#define KB_OFF (2 * 128 * STRW)           // 33792
#define MISC_F (3 * 128 * STRW)           // 50688
#define SMEM_BYTES ((MISC_F + 384) * 4)   // 204288

__global__ void __launch_bounds__(256, 1)
fusedMMA(const float* __restrict__ memory, const float* __restrict__ pos,
         const float* __restrict__ bp) {
    extern __shared__ u32 sh[];
    u32* Ab = sh + AB_OFF;
    u32* Wb = sh + WB_OFF;
    u32* Kb = sh + KB_OFF;
    float* sRsq  = (float*)(sh + MISC_F);
    float* sBias = sRsq + 128;

    const int tid = threadIdx.x, lane = tid & 31, w = tid >> 5;
    const int gid = lane >> 2, tig = lane & 3;
    const int n = blockIdx.y;
    const int row0 = blockIdx.x * 128;
    const int r0 = w * 16 + gid;

    sBias[tid] = bp[tid];

    // stage A = bf16(memory + pos): [srow][c], stride 132 words
#pragma unroll 4
    for (int it = 0; it < 16; it++) {
        int idx = tid + it * 256;
        int srow = idx >> 5, cg = (idx & 31) * 8;
        int ga = ((row0 + srow) * N_ + n) * C_ + cg;
        float4 m0 = *(const float4*)(memory + ga);
        float4 m1 = *(const float4*)(memory + ga + 4);
        float4 p0 = *(const float4*)(pos + ga);
        float4 p1 = *(const float4*)(pos + ga + 4);
        u32 x0 = bfp(m0.x + p0.x, m0.y + p0.y);
        u32 x1 = bfp(m0.z + p0.z, m0.w + p0.w);
        u32 x2 = bfp(m1.x + p1.x, m1.y + p1.y);
        u32 x3 = bfp(m1.z + p1.z, m1.w + p1.w);
        ull* d = (ull*)(Ab + srow * STRW + (cg >> 1));
        d[0] = ((ull)x1 << 32) | x0;
        d[1] = ((ull)x3 << 32) | x2;
    }
    // stage Wp half 0
    for (int i = tid; i < 16384; i += 256)
        Wb[(i >> 7) * STRW + (i & 127)] = g_WpB[i];
    __syncthreads();

    float ssl = 0.f, ssh = 0.f;
    // ---------------- phase 1: kp = A @ Wp^T (two j-halves) ------------------
#pragma unroll 1
    for (int h = 0; h < 2; h++) {
        float acc[16][4];
#pragma unroll
        for (int nt = 0; nt < 16; nt++)
#pragma unroll
            for (int i = 0; i < 4; i++) acc[nt][i] = 0.f;

#pragma unroll 4
        for (int ks = 0; ks < 16; ks++) {
            int kw = ks * 8;
            u32 a0 = Ab[r0 * STRW + kw + tig];
            u32 a1 = Ab[(r0 + 8) * STRW + kw + tig];
            u32 a2 = Ab[r0 * STRW + kw + 4 + tig];
            u32 a3 = Ab[(r0 + 8) * STRW + kw + 4 + tig];
#pragma unroll
            for (int nt = 0; nt < 16; nt++) {
                int br = (nt * 8 + gid) * STRW + kw;
                u32 b0 = Wb[br + tig];
                u32 b1 = Wb[br + 4 + tig];
                MMA16816(acc[nt], a0, a1, a2, a3, b0, b1);
            }
        }
        __syncthreads();   // all warps done reading Wb (and Ab for this h)

        // epilogue: +bias, store bf16 kp, accumulate norms
#pragma unroll
        for (int nt = 0; nt < 16; nt++) {
            int j = h * 128 + nt * 8 + tig * 2;
            float b0f = sBias[j], b1f = sBias[j + 1];
            float v0 = acc[nt][0] + b0f, v1 = acc[nt][1] + b1f;
            float v2 = acc[nt][2] + b0f, v3 = acc[nt][3] + b1f;
            Kb[r0 * STRW + (j >> 1)] = bfp(v0, v1);
            Kb[(r0 + 8) * STRW + (j >> 1)] = bfp(v2, v3);
            ssl = fmaf(v0, v0, fmaf(v1, v1, ssl));
            ssh = fmaf(v2, v2, fmaf(v3, v3, ssh));
        }
        if (h == 0) {
            for (int i = tid; i < 16384; i += 256)
                Wb[(i >> 7) * STRW + (i & 127)] = g_WpB[16384 + i];
            __syncthreads();
        }
    }

    // norms: reduce within quad (lanes differ only in tig)
    ssl += __shfl_xor_sync(0xFFFFFFFFu, ssl, 1);
    ssl += __shfl_xor_sync(0xFFFFFFFFu, ssl, 2);
    ssh += __shfl_xor_sync(0xFFFFFFFFu, ssh, 1);
    ssh += __shfl_xor_sync(0xFFFFFFFFu, ssh, 2);
    if (tig == 0) {
        sRsq[r0]     = 1.0f / fmaxf(sqrtf(ssl), 1e-12f);
        sRsq[r0 + 8] = 1.0f / fmaxf(sqrtf(ssh), 1e-12f);
    }

    // stage Q (bf16) into Ab
    for (int i = tid; i < 16384; i += 256)
        Ab[(i >> 7) * STRW + (i & 127)] = g_qB[n * 16384 + i];
    __syncthreads();

    // ---------------- phase 2: logits = Q @ kp^T -----------------------------
    float acc[16][4];
#pragma unroll
    for (int nt = 0; nt < 16; nt++)
#pragma unroll
        for (int i = 0; i < 4; i++) acc[nt][i] = 0.f;

#pragma unroll 4
    for (int ks = 0; ks < 16; ks++) {
        int kw = ks * 8;
        u32 a0 = Ab[r0 * STRW + kw + tig];
        u32 a1 = Ab[(r0 + 8) * STRW + kw + tig];
        u32 a2 = Ab[r0 * STRW + kw + 4 + tig];
        u32 a3 = Ab[(r0 + 8) * STRW + kw + 4 + tig];
#pragma unroll
        for (int nt = 0; nt < 16; nt++) {
            int br = (nt * 8 + gid) * STRW + kw;
            u32 b0 = Kb[br + tig];
            u32 b1 = Kb[br + 4 + tig];
            MMA16816(acc[nt], a0, a1, a2, a3, b0, b1);
        }
    }

    // epilogue 2: scale by rsq, argmax + candidates
    float bvl = -1e30f, bvh = -1e30f;
    int bsl = 0, bsh = 0;
#pragma unroll
    for (int nt = 0; nt < 16; nt++) {
        int s0 = nt * 8 + tig * 2;
        float r0s = sRsq[s0], r1s = sRsq[s0 + 1];
        float v0 = acc[nt][0] * r0s, v1 = acc[nt][1] * r1s;
        float v2 = acc[nt][2] * r0s, v3 = acc[nt][3] * r1s;
        if (v0 > bvl) { bvl = v0; bsl = s0; }
        if (v1 > bvl) { bvl = v1; bsl = s0 + 1; }
        if (v2 > bvh) { bvh = v2; bsh = s0; }
        if (v3 > bvh) { bvh = v3; bsh = s0 + 1; }
    }
    ull pl = ((ull)fkey(bvl) << 32) | (ull)(0xFFFFFFFFu - (u32)(row0 + bsl));
    ull ph = ((ull)fkey(bvh) << 32) | (ull)(0xFFFFFFFFu - (u32)(row0 + bsh));
#pragma unroll
    for (int m = 1; m <= 2; m <<= 1) {
        ull o = __shfl_xor_sync(0xFFFFFFFFu, pl, m); if (o > pl) pl = o;
        o = __shfl_xor_sync(0xFFFFFFFFu, ph, m); if (o > ph) ph = o;
    }
    if (tig == 0) {
        atomicMax(&g_bestA[n * L_ + r0], pl);
        atomicMax(&g_bestA[n * L_ + r0 + 8], ph);
    }
    float thrl = unfkey((u32)(pl >> 32)) - MARGIN;
    float thrh = unfkey((u32)(ph >> 32)) - MARGIN;
#pragma unroll
    for (int nt = 0; nt < 16; nt++) {
        int s0 = nt * 8 + tig * 2;
        float r0s = sRsq[s0], r1s = sRsq[s0 + 1];
        float v[4] = { acc[nt][0] * r0s, acc[nt][1] * r1s,
                       acc[nt][2] * r0s, acc[nt][3] * r1s };
#pragma unroll
        for (int i = 0; i < 4; i++) {
            float thr = (i < 2) ? thrl : thrh;
            if (v[i] >= thr) {
                int l = (i < 2) ? r0 : (r0 + 8);
                int s = row0 + s0 + (i & 1);
                int ci = atomicAdd(&g_ncand, 1);
                if (ci < CAND_CAP)
                    g_cand[ci] = make_uint4((u32)n, (u32)l, (u32)s,
                                            __float_as_uint(v[i]));
            }
        }
    }
}

// ---------------- filter: keep candidates near global approx max ------------
__global__ void __launch_bounds__(256)
filterKernel() {
    int nc = g_ncand; if (nc > CAND_CAP) nc = CAND_CAP;
    for (int i = blockIdx.x * blockDim.x + threadIdx.x; i < nc;
         i += gridDim.x * blockDim.x) {
        uint4 e = g_cand[i];
        float gmax = unfkey((u32)(g_bestA[e.x * L_ + e.y] >> 32));
        if (__uint_as_float(e.w) >= gmax - MARGIN) {
            int si = atomicAdd(&g_nsurv, 1);
            if (si < SURV_CAP) g_surv[si] = e;
        }
    }
}

// ---------------- refine: exact fp32 logits for survivors -------------------
__global__ void __launch_bounds__(256)
refineKernel(const float* __restrict__ memory, const float* __restrict__ pos,
             const float* __restrict__ bp) {
    __shared__ float aS[8 * 260];
    __shared__ float qS[8 * 260];
    __shared__ float red[2][8][8];
    __shared__ uint4 eS[8];
    const int tid = threadIdx.x;
    int nsurv = g_nsurv; if (nsurv > SURV_CAP) nsurv = SURV_CAP;
    int ngroups = (nsurv + 7) >> 3;

    for (int g = blockIdx.x; g < ngroups; g += gridDim.x) {
        if (tid < 8) {
            int i = g * 8 + tid;
            eS[tid] = (i < nsurv) ? g_surv[i] : make_uint4(0, 0, 0xFFFFFFFFu, 0);
        }
        __syncthreads();
#pragma unroll
        for (int r = 0; r < 8; r++) {
            uint4 e = eS[r];
            int s = (e.z == 0xFFFFFFFFu) ? 0 : (int)e.z;
            int ga = (s * N_ + (int)e.x) * C_ + tid;
            aS[r * 260 + tid] = memory[ga] + pos[ga];
            qS[r * 260 + tid] = g_qproj[((int)e.x * L_ + (int)e.y) * C_ + tid];
        }
        __syncthreads();

        const int j = tid;
        float kp[8];
#pragma unroll
        for (int r = 0; r < 8; r++) kp[r] = bp[j];
#pragma unroll 4
        for (int c = 0; c < C_; c++) {
            float wv = g_WpT[c * C_ + j];
#pragma unroll
            for (int r = 0; r < 8; r++) kp[r] = fmaf(aS[r * 260 + c], wv, kp[r]);
        }
        const int lane = tid & 31, wrp = tid >> 5;
#pragma unroll
        for (int r = 0; r < 8; r++) {
            float v2 = kp[r] * kp[r];
            float vq = kp[r] * qS[r * 260 + j];
#pragma unroll
            for (int m = 16; m >= 1; m >>= 1) {
                v2 += __shfl_xor_sync(0xFFFFFFFFu, v2, m);
                vq += __shfl_xor_sync(0xFFFFFFFFu, vq, m);
            }
            if (lane == 0) { red[0][r][wrp] = v2; red[1][r][wrp] = vq; }
        }
        __syncthreads();
        if (tid < 8) {
            const int r = tid;
            float ss = 0.f, qq = 0.f;
#pragma unroll
            for (int ww = 0; ww < 8; ww++) { ss += red[0][r][ww]; qq += red[1][r][ww]; }
            uint4 e = eS[r];
            if (e.z != 0xFFFFFFFFu) {
                float rsq = 1.0f / fmaxf(sqrtf(ss), 1e-12f);
                float logit = qq * rsq;
                atomicMax(&g_bestE[e.x * L_ + e.y],
                          ((ull)fkey(logit) << 32) | (ull)(0xFFFFFFFFu - e.z));
            }
        }
        __syncthreads();
    }
}

// ---------------- epilogue: winners -> v -> upd -> residual + LN ------------
__device__ __forceinline__ void gemvT(const float* inb, float* outb,
                                      const float* __restrict__ WT,
                                      const float* __restrict__ bias, int j) {
    float acc[8];
#pragma unroll
    for (int r = 0; r < 8; r++) acc[r] = bias[j];
#pragma unroll 4
    for (int c = 0; c < C_; c++) {
        float wv = WT[c * C_ + j];
#pragma unroll
        for (int r = 0; r < 8; r++) acc[r] = fmaf(inb[r * 260 + c], wv, acc[r]);
    }
#pragma unroll
    for (int r = 0; r < 8; r++) outb[r * 260 + j] = acc[r];
}

__global__ void __launch_bounds__(256)
finalKernel(const float* __restrict__ tgt, const float* __restrict__ memory,
            const float* __restrict__ pos,
            const float* __restrict__ bp, const float* __restrict__ bv,
            const float* __restrict__ bo,
            const float* __restrict__ gamma, const float* __restrict__ beta,
            float* __restrict__ out) {
    __shared__ float bufX[8 * 260];
    __shared__ float bufY[8 * 260];
    __shared__ unsigned sidx[8];
    const int tid = threadIdx.x;
    const int b = blockIdx.x;
    const int n = b >> 4;

    if (tid < 8) {
        ull pk = g_bestE[b * 8 + tid];
        sidx[tid] = 0xFFFFFFFFu - (unsigned)(pk & 0xFFFFFFFFu);
    }
    __syncthreads();

    for (int idx = tid; idx < 8 * 256; idx += 256) {
        int r = idx >> 8, j = idx & 255;
        int s = (int)sidx[r];
        int g = (s * N_ + n) * C_ + j;
        bufX[r * 260 + j] = memory[g] + pos[g];
    }
    __syncthreads();
    gemvT(bufX, bufY, g_WpT, bp, tid);  __syncthreads();
    gemvT(bufY, bufX, g_WvT, bv, tid);  __syncthreads();
    gemvT(bufX, bufY, g_WoT, bo, tid);  __syncthreads();

#pragma unroll
    for (int r = 0; r < 8; r++) {
        int l = (b & 15) * 8 + r;
        bufY[r * 260 + tid] += tgt[(l * N_ + n) * C_ + tid];
    }
    __syncthreads();

    const int w = tid >> 5, lane = tid & 31;
    float s1 = 0.f, s2 = 0.f;
#pragma unroll
    for (int k = 0; k < 8; k++) {
        float v = bufY[w * 260 + lane + k * 32];
        s1 += v;
        s2 = fmaf(v, v, s2);
    }
#pragma unroll
    for (int m = 16; m >= 1; m >>= 1) {
        s1 += __shfl_xor_sync(0xFFFFFFFFu, s1, m);
        s2 += __shfl_xor_sync(0xFFFFFFFFu, s2, m);
    }
    float mu = s1 * (1.0f / 256.0f);
    float var = s2 * (1.0f / 256.0f) - mu * mu;
    float rstd = rsqrtf(var + 1e-5f);

    int l = (b & 15) * 8 + w;
    float* o = out + (l * N_ + n) * C_;
#pragma unroll
    for (int k = 0; k < 8; k++) {
        int j = lane + k * 32;
        float v = bufY[w * 260 + j];
        o[j] = (v - mu) * rstd * gamma[j] + beta[j];
    }
}

// ============================================================================
extern "C" void kernel_launch(void* const* d_in, const int* in_sizes, int n_in,
                              void* d_out, int out_size) {
    const float* tgt    = (const float*)d_in[0];
    const float* memory = (const float*)d_in[1];
    const float* pos    = (const float*)d_in[2];
    const float* qpos   = (const float*)d_in[3];
    const float* Wq     = (const float*)d_in[4];
    const float* bq     = (const float*)d_in[5];
    const float* Wp     = (const float*)d_in[6];
    const float* bp     = (const float*)d_in[7];
    const float* Wv     = (const float*)d_in[8];
    const float* bv     = (const float*)d_in[9];
    const float* Wo     = (const float*)d_in[10];
    const float* bo     = (const float*)d_in[11];
    const float* gamma  = (const float*)d_in[12];
    const float* beta   = (const float*)d_in[13];
    float* out = (float*)d_out;

    cudaFuncSetAttribute(fusedMMA, cudaFuncAttributeMaxDynamicSharedMemorySize,
                         SMEM_BYTES);

    initKernel<<<1, N_ * L_>>>();
    convWKernel<<<256, 256>>>(Wp, Wv, Wo);
    qprojKernel<<<64, 256>>>(tgt, qpos, Wq, bq);
    fusedMMA<<<dim3(S_ / 128, N_), 256, SMEM_BYTES>>>(memory, pos, bp);
    filterKernel<<<128, 256>>>();
    refineKernel<<<128, 256>>>(memory, pos, bp);
    finalKernel<<<128, 256>>>(tgt, memory, pos, bp, bv, bo, gamma, beta, out);
}

// round 7
// speedup vs baseline: 2.5937x; 1.3049x over previous
#include <cuda_runtime.h>
#include <cstdint>
#include <math.h>

#define L_ 128
#define N_ 8
#define S_ 16384
#define C_ 256
#define MARGIN 0.15f
#define CAND_CAP (1 << 20)
#define SURV_CAP (1 << 18)

typedef unsigned long long ull;
typedef unsigned int u32;

// ---------------- device scratch (no allocations allowed) -------------------
__device__ float g_qproj[N_ * L_ * C_];          // exact fp32 q_proj [n][l][c]
__device__ u32   g_qB[N_ * L_ * C_ / 2];         // bf16x2 Q, [n][l][c/2]
__device__ u32   g_WpB[C_ * C_ / 2];             // bf16x2 Wp, [j][c/2] linear
__device__ float g_WpT[C_ * C_];                 // fp32 transposed weights [c][j]
__device__ float g_WvT[C_ * C_];
__device__ float g_WoT[C_ * C_];
__device__ ull   g_bestA[N_ * L_];               // approx packed max
__device__ ull   g_bestE[N_ * L_];               // exact packed max
__device__ int   g_ncand, g_nsurv;
__device__ uint4 g_cand[CAND_CAP];               // {n, l, s, approx_bits}
__device__ uint4 g_surv[SURV_CAP];

// ---------------- small helpers --------------------------------------------
__device__ __forceinline__ ull pk2(float a, float b) {
    ull r; asm("mov.b64 %0, {%1, %2};" : "=l"(r) : "f"(a), "f"(b)); return r;
}
__device__ __forceinline__ void up2(ull v, float &a, float &b) {
    asm("mov.b64 {%0, %1}, %2;" : "=f"(a), "=f"(b) : "l"(v));
}
#define FMA2(d, a, b) asm("fma.rn.f32x2 %0, %1, %2, %0;" : "+l"(d) : "l"(a), "l"(b))

__device__ __forceinline__ u32 fkey(float f) {
    u32 u = __float_as_uint(f);
    return (u & 0x80000000u) ? ~u : (u | 0x80000000u);
}
__device__ __forceinline__ float unfkey(u32 k) {
    return (k & 0x80000000u) ? __uint_as_float(k & 0x7FFFFFFFu)
                             : __uint_as_float(~k);
}
__device__ __forceinline__ u32 bfp(float lo, float hi) {   // bf16x2 {hi|lo}
    u32 r; asm("cvt.rn.bf16x2.f32 %0, %1, %2;" : "=r"(r) : "f"(hi), "f"(lo));
    return r;
}

// mma.sync m16n8k16 row.col bf16 -> f32 accum
#define MMA16816(c, a0, a1, a2, a3, b0, b1) \
    asm volatile("mma.sync.aligned.m16n8k16.row.col.f32.bf16.bf16.f32 " \
        "{%0,%1,%2,%3}, {%4,%5,%6,%7}, {%8,%9}, {%0,%1,%2,%3};" \
        : "+f"((c)[0]), "+f"((c)[1]), "+f"((c)[2]), "+f"((c)[3]) \
        : "r"(a0), "r"(a1), "r"(a2), "r"(a3), "r"(b0), "r"(b1))

// ---------------- weight prep: transposes + bf16 Wp + init ------------------
__global__ void __launch_bounds__(256)
convWKernel(const float* __restrict__ Wp, const float* __restrict__ Wv,
            const float* __restrict__ Wo) {
    int j = blockIdx.x;
    int c = threadIdx.x;
    if (j < 4) {
        int i = j * 256 + c;
        ull iv = ((ull)fkey(-1e30f)) << 32;
        g_bestA[i] = iv;
        g_bestE[i] = iv;
        if (i == 0) { g_ncand = 0; g_nsurv = 0; }
    }
    float wp = Wp[j * C_ + c];
    g_WpT[c * C_ + j] = wp;
    g_WvT[c * C_ + j] = Wv[j * C_ + c];
    g_WoT[c * C_ + j] = Wo[j * C_ + c];
    if ((c & 1) == 0) {
        float wp1 = Wp[j * C_ + c + 1];
        g_WpB[j * 128 + (c >> 1)] = bfp(wp, wp1);
    }
}

// ---------------- exact fp32 q_proj (FFMA2), 64 blocks x 16 rows ------------
__global__ void __launch_bounds__(256)
qprojKernel(const float* __restrict__ tgt, const float* __restrict__ qpos,
            const float* __restrict__ Wq, const float* __restrict__ bq) {
    __shared__ float As[16 * 33];
    __shared__ float Bs[32 * 258];
    const int tid = threadIdx.x;
    const int tj = tid & 15;
    const int ts = tid >> 4;
    const int row0 = blockIdx.x * 16;

    ull acc[8];
#pragma unroll
    for (int k = 0; k < 8; k++) {
        int j = 32 * k + tj * 2;
        acc[k] = pk2(bq[j], bq[j + 1]);
    }

    for (int kc = 0; kc < C_; kc += 32) {
        if (tid < 128) {
            int lr = tid >> 3, c4 = (tid & 7) * 4;
            int g = (row0 + lr) * C_ + kc + c4;
            float4 a = *(const float4*)(tgt + g);
            float4 b = *(const float4*)(qpos + g);
            float* d = As + lr * 33 + c4;
            d[0] = a.x + b.x; d[1] = a.y + b.y; d[2] = a.z + b.z; d[3] = a.w + b.w;
        }
        {
            int lr = tid >> 1, lh = tid & 1;
#pragma unroll
            for (int it = 0; it < 2; it++) {
                int j = lr + it * 128;
                const float4* pw = (const float4*)(Wq + j * C_ + kc + lh * 16);
#pragma unroll
                for (int i = 0; i < 4; i++) {
                    float4 w = pw[i];
                    int c = lh * 16 + i * 4;
                    Bs[(c + 0) * 258 + j] = w.x;
                    Bs[(c + 1) * 258 + j] = w.y;
                    Bs[(c + 2) * 258 + j] = w.z;
                    Bs[(c + 3) * 258 + j] = w.w;
                }
            }
        }
        __syncthreads();
#pragma unroll 4
        for (int c = 0; c < 32; c++) {
            float av = As[ts * 33 + c];
            ull a2 = pk2(av, av);
#pragma unroll
            for (int k = 0; k < 8; k++) {
                ull b2 = *(const ull*)(Bs + c * 258 + 32 * k + tj * 2);
                FMA2(acc[k], a2, b2);
            }
        }
        __syncthreads();
    }

    int row = row0 + ts;
    int l = row >> 3, n = row & 7;
    float* of = g_qproj + (n * L_ + l) * C_;
#pragma unroll
    for (int k = 0; k < 8; k++) {
        int j = 32 * k + tj * 2;
        *(ull*)(of + j) = acc[k];
        float f0, f1; up2(acc[k], f0, f1);
        g_qB[n * 16384 + l * 128 + (j >> 1)] = bfp(f0, f1);
    }
}

// ---------------- fused mma.sync kernel (occ 2) -----------------------------
// Tile: 64 s-rows per block. grid (256, 8).
#define STRW 132                          // u32 words per smem row
#define AB_OFF 0
#define KB_OFF (64 * STRW)                // 8448
#define WS_OFF (2 * 64 * STRW)            // 16896
#define NRM_F (3 * 64 * STRW)             // 25344 (floats: sNorm[64][2])
#define RSQ_F (NRM_F + 128)               // sRsq[64]
#define BIA_F (RSQ_F + 64)                // sBias[256]
#define SMEM_WORDS (BIA_F + 256)          // 25792
#define SMEM_BYTES (SMEM_WORDS * 4)       // 103168

__global__ void __launch_bounds__(256, 2)
fusedMMA(const float* __restrict__ memory, const float* __restrict__ pos,
         const float* __restrict__ bp) {
    extern __shared__ u32 sh[];
    u32* Ab = sh + AB_OFF;
    u32* Kb = sh + KB_OFF;
    u32* Ws = sh + WS_OFF;
    float* sNorm = (float*)(sh + NRM_F);   // [row][wj]
    float* sRsq  = (float*)(sh + RSQ_F);
    float* sBias = (float*)(sh + BIA_F);

    const int tid = threadIdx.x, lane = tid & 31, w = tid >> 5;
    const int gid = lane >> 2, tig = lane & 3;
    const int wm = w >> 1, wj = w & 1;
    const int n = blockIdx.y;
    const int srow0 = blockIdx.x * 64;
    const int r0 = wm * 16 + gid;          // row pair r0, r0+8 (0..63)

    sBias[tid] = bp[tid];

    // ---- stage A = bf16(memory + pos): 64 rows x 256 c ----------------------
#pragma unroll
    for (int it = 0; it < 8; it++) {
        int idx = tid + it * 256;
        int srow = idx >> 5, cg = (idx & 31) * 8;
        int ga = ((srow0 + srow) * N_ + n) * C_ + cg;
        float4 m0 = *(const float4*)(memory + ga);
        float4 m1 = *(const float4*)(memory + ga + 4);
        float4 p0 = *(const float4*)(pos + ga);
        float4 p1 = *(const float4*)(pos + ga + 4);
        uint4 x;
        x.x = bfp(m0.x + p0.x, m0.y + p0.y);
        x.y = bfp(m0.z + p0.z, m0.w + p0.w);
        x.z = bfp(m1.x + p1.x, m1.y + p1.y);
        x.w = bfp(m1.z + p1.z, m1.w + p1.w);
        *(uint4*)(Ab + srow * STRW + (cg >> 1)) = x;
    }
    // ---- stage W quarter 0 (64 j-rows x 128 words) --------------------------
#pragma unroll
    for (int it = 0; it < 8; it++) {
        int i = tid + it * 256;
        int row = i >> 5, c4 = (i & 31) * 4;
        *(uint4*)(Ws + row * STRW + c4) = *(const uint4*)(g_WpB + row * 128 + c4);
    }
    __syncthreads();

    float ss0 = 0.f, ss1 = 0.f;
    // ---- phase 1: kp = A @ Wp^T, four 64-j quarters -------------------------
#pragma unroll 1
    for (int q = 0; q < 4; q++) {
        float acc[4][4];
#pragma unroll
        for (int nt = 0; nt < 4; nt++)
#pragma unroll
            for (int i = 0; i < 4; i++) acc[nt][i] = 0.f;

#pragma unroll 4
        for (int ks = 0; ks < 16; ks++) {
            int kw = ks * 8;
            u32 a0 = Ab[r0 * STRW + kw + tig];
            u32 a1 = Ab[(r0 + 8) * STRW + kw + tig];
            u32 a2 = Ab[r0 * STRW + kw + 4 + tig];
            u32 a3 = Ab[(r0 + 8) * STRW + kw + 4 + tig];
#pragma unroll
            for (int nt = 0; nt < 4; nt++) {
                int br = (wj * 32 + nt * 8 + gid) * STRW + kw;
                u32 b0 = Ws[br + tig];
                u32 b1 = Ws[br + 4 + tig];
                MMA16816(acc[nt], a0, a1, a2, a3, b0, b1);
            }
        }
        __syncthreads();   // all warps done reading Ws

        // epilogue: +bias, bf16 kp -> Kb, accumulate norm partials
#pragma unroll
        for (int nt = 0; nt < 4; nt++) {
            int jg = q * 64 + wj * 32 + nt * 8 + tig * 2;
            float b0f = sBias[jg], b1f = sBias[jg + 1];
            float v0 = acc[nt][0] + b0f, v1 = acc[nt][1] + b1f;
            float v2 = acc[nt][2] + b0f, v3 = acc[nt][3] + b1f;
            Kb[r0 * STRW + (jg >> 1)] = bfp(v0, v1);
            Kb[(r0 + 8) * STRW + (jg >> 1)] = bfp(v2, v3);
            ss0 = fmaf(v0, v0, fmaf(v1, v1, ss0));
            ss1 = fmaf(v2, v2, fmaf(v3, v3, ss1));
        }
        if (q < 3) {   // restage next W quarter
            const u32* src = g_WpB + (q + 1) * 64 * 128;
#pragma unroll
            for (int it = 0; it < 8; it++) {
                int i = tid + it * 256;
                int row = i >> 5, c4 = (i & 31) * 4;
                *(uint4*)(Ws + row * STRW + c4) = *(const uint4*)(src + row * 128 + c4);
            }
        } else {       // last quarter: stage Q half 0 instead + write norms
            ss0 += __shfl_xor_sync(0xFFFFFFFFu, ss0, 1);
            ss0 += __shfl_xor_sync(0xFFFFFFFFu, ss0, 2);
            ss1 += __shfl_xor_sync(0xFFFFFFFFu, ss1, 1);
            ss1 += __shfl_xor_sync(0xFFFFFFFFu, ss1, 2);
            if (tig == 0) {
                sNorm[r0 * 2 + wj] = ss0;
                sNorm[(r0 + 8) * 2 + wj] = ss1;
            }
            const u32* src = g_qB + n * 16384;
#pragma unroll
            for (int it = 0; it < 8; it++) {
                int i = tid + it * 256;
                int row = i >> 5, c4 = (i & 31) * 4;
                *(uint4*)(Ws + row * STRW + c4) = *(const uint4*)(src + row * 128 + c4);
            }
        }
        __syncthreads();
    }

    // rsq
    if (tid < 64)
        sRsq[tid] = 1.0f / fmaxf(sqrtf(sNorm[tid * 2] + sNorm[tid * 2 + 1]), 1e-12f);
    __syncthreads();

    // ---- phase 2: logits = Q @ kp^T, two 64-l halves ------------------------
#pragma unroll 1
    for (int h = 0; h < 2; h++) {
        float acc[4][4];
#pragma unroll
        for (int nt = 0; nt < 4; nt++)
#pragma unroll
            for (int i = 0; i < 4; i++) acc[nt][i] = 0.f;

#pragma unroll 4
        for (int ks = 0; ks < 16; ks++) {
            int kw = ks * 8;
            u32 a0 = Ws[r0 * STRW + kw + tig];
            u32 a1 = Ws[(r0 + 8) * STRW + kw + tig];
            u32 a2 = Ws[r0 * STRW + kw + 4 + tig];
            u32 a3 = Ws[(r0 + 8) * STRW + kw + 4 + tig];
#pragma unroll
            for (int nt = 0; nt < 4; nt++) {
                int br = (wj * 32 + nt * 8 + gid) * STRW + kw;
                u32 b0 = Kb[br + tig];
                u32 b1 = Kb[br + 4 + tig];
                MMA16816(acc[nt], a0, a1, a2, a3, b0, b1);
            }
        }

        // epilogue2: scale, argmax, candidates
        float bv0 = -1e30f, bv1 = -1e30f;
        int bs0 = 0, bs1 = 0;
        float vv[4][4];
#pragma unroll
        for (int nt = 0; nt < 4; nt++) {
            int sl = wj * 32 + nt * 8 + tig * 2;
            float ra = sRsq[sl], rb = sRsq[sl + 1];
            vv[nt][0] = acc[nt][0] * ra; vv[nt][1] = acc[nt][1] * rb;
            vv[nt][2] = acc[nt][2] * ra; vv[nt][3] = acc[nt][3] * rb;
            if (vv[nt][0] > bv0) { bv0 = vv[nt][0]; bs0 = sl; }
            if (vv[nt][1] > bv0) { bv0 = vv[nt][1]; bs0 = sl + 1; }
            if (vv[nt][2] > bv1) { bv1 = vv[nt][2]; bs1 = sl; }
            if (vv[nt][3] > bv1) { bv1 = vv[nt][3]; bs1 = sl + 1; }
        }
        ull p0 = ((ull)fkey(bv0) << 32) | (ull)(0xFFFFFFFFu - (u32)(srow0 + bs0));
        ull p1 = ((ull)fkey(bv1) << 32) | (ull)(0xFFFFFFFFu - (u32)(srow0 + bs1));
#pragma unroll
        for (int m = 1; m <= 2; m <<= 1) {
            ull o = __shfl_xor_sync(0xFFFFFFFFu, p0, m); if (o > p0) p0 = o;
            o = __shfl_xor_sync(0xFFFFFFFFu, p1, m); if (o > p1) p1 = o;
        }
        int lg0 = h * 64 + r0, lg1 = lg0 + 8;
        ull old0 = 0, old1 = 0;
        if (tig == 0) {
            old0 = atomicMax(&g_bestA[n * L_ + lg0], p0);
            old1 = atomicMax(&g_bestA[n * L_ + lg1], p1);
        }
        old0 = __shfl_sync(0xFFFFFFFFu, old0, lane & ~3);
        old1 = __shfl_sync(0xFFFFFFFFu, old1, lane & ~3);
        float thr0 = fmaxf(unfkey((u32)(p0 >> 32)), unfkey((u32)(old0 >> 32))) - MARGIN;
        float thr1 = fmaxf(unfkey((u32)(p1 >> 32)), unfkey((u32)(old1 >> 32))) - MARGIN;
#pragma unroll
        for (int nt = 0; nt < 4; nt++) {
            int sl = wj * 32 + nt * 8 + tig * 2;
#pragma unroll
            for (int i = 0; i < 4; i++) {
                float v = vv[nt][i];
                float thr = (i < 2) ? thr0 : thr1;
                if (v >= thr) {
                    int l = (i < 2) ? lg0 : lg1;
                    int s = srow0 + sl + (i & 1);
                    int ci = atomicAdd(&g_ncand, 1);
                    if (ci < CAND_CAP)
                        g_cand[ci] = make_uint4((u32)n, (u32)l, (u32)s,
                                                __float_as_uint(v));
                }
            }
        }

        if (h == 0) {   // restage Q half 1
            __syncthreads();
            const u32* src = g_qB + n * 16384 + 64 * 128;
#pragma unroll
            for (int it = 0; it < 8; it++) {
                int i = tid + it * 256;
                int row = i >> 5, c4 = (i & 31) * 4;
                *(uint4*)(Ws + row * STRW + c4) = *(const uint4*)(src + row * 128 + c4);
            }
            __syncthreads();
        }
    }
}

// ---------------- filter: keep candidates near global approx max ------------
__global__ void __launch_bounds__(256)
filterKernel() {
    int nc = g_ncand; if (nc > CAND_CAP) nc = CAND_CAP;
    for (int i = blockIdx.x * blockDim.x + threadIdx.x; i < nc;
         i += gridDim.x * blockDim.x) {
        uint4 e = g_cand[i];
        float gmax = unfkey((u32)(g_bestA[e.x * L_ + e.y] >> 32));
        if (__uint_as_float(e.w) >= gmax - MARGIN) {
            int si = atomicAdd(&g_nsurv, 1);
            if (si < SURV_CAP) g_surv[si] = e;
        }
    }
}

// ---------------- refine: exact fp32 logits for survivors -------------------
__global__ void __launch_bounds__(256)
refineKernel(const float* __restrict__ memory, const float* __restrict__ pos,
             const float* __restrict__ bp) {
    __shared__ float aS[8 * 260];
    __shared__ float qS[8 * 260];
    __shared__ float red[2][8][8];
    __shared__ uint4 eS[8];
    const int tid = threadIdx.x;
    int nsurv = g_nsurv; if (nsurv > SURV_CAP) nsurv = SURV_CAP;
    int ngroups = (nsurv + 7) >> 3;

    for (int g = blockIdx.x; g < ngroups; g += gridDim.x) {
        if (tid < 8) {
            int i = g * 8 + tid;
            eS[tid] = (i < nsurv) ? g_surv[i] : make_uint4(0, 0, 0xFFFFFFFFu, 0);
        }
        __syncthreads();
#pragma unroll
        for (int r = 0; r < 8; r++) {
            uint4 e = eS[r];
            int s = (e.z == 0xFFFFFFFFu) ? 0 : (int)e.z;
            int ga = (s * N_ + (int)e.x) * C_ + tid;
            aS[r * 260 + tid] = memory[ga] + pos[ga];
            qS[r * 260 + tid] = g_qproj[((int)e.x * L_ + (int)e.y) * C_ + tid];
        }
        __syncthreads();

        const int j = tid;
        float kp[8];
#pragma unroll
        for (int r = 0; r < 8; r++) kp[r] = bp[j];
#pragma unroll 4
        for (int c = 0; c < C_; c++) {
            float wv = g_WpT[c * C_ + j];
#pragma unroll
            for (int r = 0; r < 8; r++) kp[r] = fmaf(aS[r * 260 + c], wv, kp[r]);
        }
        const int lane = tid & 31, wrp = tid >> 5;
#pragma unroll
        for (int r = 0; r < 8; r++) {
            float v2 = kp[r] * kp[r];
            float vq = kp[r] * qS[r * 260 + j];
#pragma unroll
            for (int m = 16; m >= 1; m >>= 1) {
                v2 += __shfl_xor_sync(0xFFFFFFFFu, v2, m);
                vq += __shfl_xor_sync(0xFFFFFFFFu, vq, m);
            }
            if (lane == 0) { red[0][r][wrp] = v2; red[1][r][wrp] = vq; }
        }
        __syncthreads();
        if (tid < 8) {
            const int r = tid;
            float ss = 0.f, qq = 0.f;
#pragma unroll
            for (int ww = 0; ww < 8; ww++) { ss += red[0][r][ww]; qq += red[1][r][ww]; }
            uint4 e = eS[r];
            if (e.z != 0xFFFFFFFFu) {
                float rsq = 1.0f / fmaxf(sqrtf(ss), 1e-12f);
                float logit = qq * rsq;
                atomicMax(&g_bestE[e.x * L_ + e.y],
                          ((ull)fkey(logit) << 32) | (ull)(0xFFFFFFFFu - e.z));
            }
        }
        __syncthreads();
    }
}

// ---------------- epilogue: winners -> v -> upd -> residual + LN ------------
__device__ __forceinline__ void gemvT(const float* inb, float* outb,
                                      const float* __restrict__ WT,
                                      const float* __restrict__ bias, int j) {
    float acc[8];
#pragma unroll
    for (int r = 0; r < 8; r++) acc[r] = bias[j];
#pragma unroll 4
    for (int c = 0; c < C_; c++) {
        float wv = WT[c * C_ + j];
#pragma unroll
        for (int r = 0; r < 8; r++) acc[r] = fmaf(inb[r * 260 + c], wv, acc[r]);
    }
#pragma unroll
    for (int r = 0; r < 8; r++) outb[r * 260 + j] = acc[r];
}

__global__ void __launch_bounds__(256)
finalKernel(const float* __restrict__ tgt, const float* __restrict__ memory,
            const float* __restrict__ pos,
            const float* __restrict__ bp, const float* __restrict__ bv,
            const float* __restrict__ bo,
            const float* __restrict__ gamma, const float* __restrict__ beta,
            float* __restrict__ out) {
    __shared__ float bufX[8 * 260];
    __shared__ float bufY[8 * 260];
    __shared__ unsigned sidx[8];
    const int tid = threadIdx.x;
    const int b = blockIdx.x;
    const int n = b >> 4;

    if (tid < 8) {
        ull pk = g_bestE[b * 8 + tid];
        sidx[tid] = 0xFFFFFFFFu - (unsigned)(pk & 0xFFFFFFFFu);
    }
    __syncthreads();

    for (int idx = tid; idx < 8 * 256; idx += 256) {
        int r = idx >> 8, j = idx & 255;
        int s = (int)sidx[r];
        int g = (s * N_ + n) * C_ + j;
        bufX[r * 260 + j] = memory[g] + pos[g];
    }
    __syncthreads();
    gemvT(bufX, bufY, g_WpT, bp, tid);  __syncthreads();
    gemvT(bufY, bufX, g_WvT, bv, tid);  __syncthreads();
    gemvT(bufX, bufY, g_WoT, bo, tid);  __syncthreads();

#pragma unroll
    for (int r = 0; r < 8; r++) {
        int l = (b & 15) * 8 + r;
        bufY[r * 260 + tid] += tgt[(l * N_ + n) * C_ + tid];
    }
    __syncthreads();

    const int w = tid >> 5, lane = tid & 31;
    float s1 = 0.f, s2 = 0.f;
#pragma unroll
    for (int k = 0; k < 8; k++) {
        float v = bufY[w * 260 + lane + k * 32];
        s1 += v;
        s2 = fmaf(v, v, s2);
    }
#pragma unroll
    for (int m = 16; m >= 1; m >>= 1) {
        s1 += __shfl_xor_sync(0xFFFFFFFFu, s1, m);
        s2 += __shfl_xor_sync(0xFFFFFFFFu, s2, m);
    }
    float mu = s1 * (1.0f / 256.0f);
    float var = s2 * (1.0f / 256.0f) - mu * mu;
    float rstd = rsqrtf(var + 1e-5f);

    int l = (b & 15) * 8 + w;
    float* o = out + (l * N_ + n) * C_;
#pragma unroll
    for (int k = 0; k < 8; k++) {
        int j = lane + k * 32;
        float v = bufY[w * 260 + j];
        o[j] = (v - mu) * rstd * gamma[j] + beta[j];
    }
}

// ============================================================================
extern "C" void kernel_launch(void* const* d_in, const int* in_sizes, int n_in,
                              void* d_out, int out_size) {
    const float* tgt    = (const float*)d_in[0];
    const float* memory = (const float*)d_in[1];
    const float* pos    = (const float*)d_in[2];
    const float* qpos   = (const float*)d_in[3];
    const float* Wq     = (const float*)d_in[4];
    const float* bq     = (const float*)d_in[5];
    const float* Wp     = (const float*)d_in[6];
    const float* bp     = (const float*)d_in[7];
    const float* Wv     = (const float*)d_in[8];
    const float* bv     = (const float*)d_in[9];
    const float* Wo     = (const float*)d_in[10];
    const float* bo     = (const float*)d_in[11];
    const float* gamma  = (const float*)d_in[12];
    const float* beta   = (const float*)d_in[13];
    float* out = (float*)d_out;

    cudaFuncSetAttribute(fusedMMA, cudaFuncAttributeMaxDynamicSharedMemorySize,
                         SMEM_BYTES);

    convWKernel<<<256, 256>>>(Wp, Wv, Wo);
    qprojKernel<<<64, 256>>>(tgt, qpos, Wq, bq);
    fusedMMA<<<dim3(S_ / 64, N_), 256, SMEM_BYTES>>>(memory, pos, bp);
    filterKernel<<<128, 256>>>();
    refineKernel<<<128, 256>>>(memory, pos, bp);
    finalKernel<<<128, 256>>>(tgt, memory, pos, bp, bv, bo, gamma, beta, out);
}

// round 8
// speedup vs baseline: 2.6467x; 1.0204x over previous
#include <cuda_runtime.h>
#include <cstdint>
#include <math.h>

#define L_ 128
#define N_ 8
#define S_ 16384
#define C_ 256
#define MARGIN 0.08f
#define CAND_CAP (1 << 20)
#define SURV_CAP (1 << 18)

typedef unsigned long long ull;
typedef unsigned int u32;

// ---------------- device scratch (no allocations allowed) -------------------
__device__ float g_qproj[N_ * L_ * C_];          // exact fp32 q_proj [n][l][c]
__device__ u32   g_qB[N_ * L_ * C_ / 2];         // bf16x2 Q, [n][l][c/2]
__device__ u32   g_WpB[C_ * C_ / 2];             // bf16x2 Wp, [j][c/2] linear
__device__ float g_WpT[C_ * C_];                 // fp32 transposed weights [c][j]
__device__ float g_WvT[C_ * C_];
__device__ float g_WoT[C_ * C_];
__device__ ull   g_bestA[N_ * L_];               // approx packed max
__device__ ull   g_bestE[N_ * L_];               // exact packed max
__device__ int   g_ncand, g_nsurv;
__device__ uint4 g_cand[CAND_CAP];               // {n, l, s, approx_bits}
__device__ uint4 g_surv[SURV_CAP];

// ---------------- small helpers --------------------------------------------
__device__ __forceinline__ ull pk2(float a, float b) {
    ull r; asm("mov.b64 %0, {%1, %2};" : "=l"(r) : "f"(a), "f"(b)); return r;
}
__device__ __forceinline__ void up2(ull v, float &a, float &b) {
    asm("mov.b64 {%0, %1}, %2;" : "=f"(a), "=f"(b) : "l"(v));
}
#define FMA2(d, a, b) asm("fma.rn.f32x2 %0, %1, %2, %0;" : "+l"(d) : "l"(a), "l"(b))

__device__ __forceinline__ u32 fkey(float f) {
    u32 u = __float_as_uint(f);
    return (u & 0x80000000u) ? ~u : (u | 0x80000000u);
}
__device__ __forceinline__ float unfkey(u32 k) {
    return (k & 0x80000000u) ? __uint_as_float(k & 0x7FFFFFFFu)
                             : __uint_as_float(~k);
}
__device__ __forceinline__ u32 bfp(float lo, float hi) {   // bf16x2 {hi|lo}
    u32 r; asm("cvt.rn.bf16x2.f32 %0, %1, %2;" : "=r"(r) : "f"(hi), "f"(lo));
    return r;
}
__device__ __forceinline__ u32 smem_u32(const void* p) {
    u32 a;
    asm("{ .reg .u64 t; cvta.to.shared.u64 t, %1; cvt.u32.u64 %0, t; }"
        : "=r"(a) : "l"(p));
    return a;
}

// mma.sync m16n8k16 row.col bf16 -> f32 accum
#define MMA16816(c, a0, a1, a2, a3, b0, b1) \
    asm volatile("mma.sync.aligned.m16n8k16.row.col.f32.bf16.bf16.f32 " \
        "{%0,%1,%2,%3}, {%4,%5,%6,%7}, {%8,%9}, {%0,%1,%2,%3};" \
        : "+f"((c)[0]), "+f"((c)[1]), "+f"((c)[2]), "+f"((c)[3]) \
        : "r"(a0), "r"(a1), "r"(a2), "r"(a3), "r"(b0), "r"(b1))

#define LDSM4(d0, d1, d2, d3, a) \
    asm volatile("ldmatrix.sync.aligned.m8n8.x4.shared.b16 {%0,%1,%2,%3}, [%4];" \
        : "=r"(d0), "=r"(d1), "=r"(d2), "=r"(d3) : "r"(a))

#define CPA16(dst, src) \
    asm volatile("cp.async.cg.shared.global [%0], [%1], 16;" \
        :: "r"(dst), "l"(src))
#define CPA_COMMIT() asm volatile("cp.async.commit_group;")
#define CPA_WAIT1()  asm volatile("cp.async.wait_group 1;")
#define CPA_WAIT0()  asm volatile("cp.async.wait_group 0;")

// ---------------- weight prep: transposes + bf16 Wp + init ------------------
__global__ void __launch_bounds__(256)
convWKernel(const float* __restrict__ Wp, const float* __restrict__ Wv,
            const float* __restrict__ Wo) {
    int j = blockIdx.x;
    int c = threadIdx.x;
    if (j < 4) {
        int i = j * 256 + c;
        ull iv = ((ull)fkey(-1e30f)) << 32;
        g_bestA[i] = iv;
        g_bestE[i] = iv;
        if (i == 0) { g_ncand = 0; g_nsurv = 0; }
    }
    float wp = Wp[j * C_ + c];
    g_WpT[c * C_ + j] = wp;
    g_WvT[c * C_ + j] = Wv[j * C_ + c];
    g_WoT[c * C_ + j] = Wo[j * C_ + c];
    if ((c & 1) == 0) {
        float wp1 = Wp[j * C_ + c + 1];
        g_WpB[j * 128 + (c >> 1)] = bfp(wp, wp1);
    }
}

// ---------------- exact fp32 q_proj (FFMA2), 64 blocks x 16 rows ------------
__global__ void __launch_bounds__(256)
qprojKernel(const float* __restrict__ tgt, const float* __restrict__ qpos,
            const float* __restrict__ Wq, const float* __restrict__ bq) {
    __shared__ float As[16 * 33];
    __shared__ float Bs[32 * 258];
    const int tid = threadIdx.x;
    const int tj = tid & 15;
    const int ts = tid >> 4;
    const int row0 = blockIdx.x * 16;

    ull acc[8];
#pragma unroll
    for (int k = 0; k < 8; k++) {
        int j = 32 * k + tj * 2;
        acc[k] = pk2(bq[j], bq[j + 1]);
    }

    for (int kc = 0; kc < C_; kc += 32) {
        if (tid < 128) {
            int lr = tid >> 3, c4 = (tid & 7) * 4;
            int g = (row0 + lr) * C_ + kc + c4;
            float4 a = *(const float4*)(tgt + g);
            float4 b = *(const float4*)(qpos + g);
            float* d = As + lr * 33 + c4;
            d[0] = a.x + b.x; d[1] = a.y + b.y; d[2] = a.z + b.z; d[3] = a.w + b.w;
        }
        {
            int lr = tid >> 1, lh = tid & 1;
#pragma unroll
            for (int it = 0; it < 2; it++) {
                int j = lr + it * 128;
                const float4* pw = (const float4*)(Wq + j * C_ + kc + lh * 16);
#pragma unroll
                for (int i = 0; i < 4; i++) {
                    float4 w = pw[i];
                    int c = lh * 16 + i * 4;
                    Bs[(c + 0) * 258 + j] = w.x;
                    Bs[(c + 1) * 258 + j] = w.y;
                    Bs[(c + 2) * 258 + j] = w.z;
                    Bs[(c + 3) * 258 + j] = w.w;
                }
            }
        }
        __syncthreads();
#pragma unroll 4
        for (int c = 0; c < 32; c++) {
            float av = As[ts * 33 + c];
            ull a2 = pk2(av, av);
#pragma unroll
            for (int k = 0; k < 8; k++) {
                ull b2 = *(const ull*)(Bs + c * 258 + 32 * k + tj * 2);
                FMA2(acc[k], a2, b2);
            }
        }
        __syncthreads();
    }

    int row = row0 + ts;
    int l = row >> 3, n = row & 7;
    float* of = g_qproj + (n * L_ + l) * C_;
#pragma unroll
    for (int k = 0; k < 8; k++) {
        int j = 32 * k + tj * 2;
        *(ull*)(of + j) = acc[k];
        float f0, f1; up2(acc[k], f0, f1);
        g_qB[n * 16384 + l * 128 + (j >> 1)] = bfp(f0, f1);
    }
}

// ---------------- fused mma.sync kernel (occ 2, ldmatrix + cp.async) --------
// Tile: 64 s-rows per block; grid (256, 8).
// smem words: Ab 8448 | Kb 8448 | Ws 2x4224 | sNorm 128 | sRsq 64 | sBias 256
//             sBest 256 (128 ull) | sThr 32
#define STRW 132
#define SMEM_WORDS 26080
#define SMEM_BYTES (SMEM_WORDS * 4)     // 104320

__global__ void __launch_bounds__(256, 2)
fusedMMA(const float* __restrict__ memory, const float* __restrict__ pos,
         const float* __restrict__ bp) {
    extern __shared__ u32 sh[];
    u32* Kb = sh + 8448;
    float* sNorm = (float*)(sh + 25344);
    float* sRsq  = (float*)(sh + 25472);
    float* sBias = (float*)(sh + 25536);
    ull*   sBest = (ull*)(sh + 25792);
    float* sThr  = (float*)(sh + 26048);

    const int tid = threadIdx.x, lane = tid & 31, w = tid >> 5;
    const int gid = lane >> 2, tig = lane & 3;
    const int wm = w >> 1, wj = w & 1;      // phase-1 roles (rows x j-half)
    const int n = blockIdx.y;
    const int srow0 = blockIdx.x * 64;

    const u32 shB = smem_u32(sh);
    const u32 AbB = shB;
    const u32 KbB = shB + 33792;
    const u32 WsB = shB + 67584;

    sBias[tid] = bp[tid];

    // ---- issue W chunks 0,1 via cp.async --------------------------------
#pragma unroll
    for (int it = 0; it < 4; it++) {
        int idx = tid + it * 256;
        int row = idx >> 5, c4 = (idx & 31) * 4;
        CPA16(WsB + row * 528 + c4 * 4, g_WpB + row * 128 + c4);
    }
    CPA_COMMIT();
#pragma unroll
    for (int it = 0; it < 4; it++) {
        int idx = tid + it * 256;
        int row = idx >> 5, c4 = (idx & 31) * 4;
        CPA16(WsB + 16896 + row * 528 + c4 * 4, g_WpB + 4096 + row * 128 + c4);
    }
    CPA_COMMIT();

    // ---- stage A = bf16(memory + pos): 64 rows x 256 c -------------------
#pragma unroll
    for (int it = 0; it < 8; it++) {
        int idx = tid + it * 256;
        int srow = idx >> 5, cg = (idx & 31) * 8;
        int ga = ((srow0 + srow) * N_ + n) * C_ + cg;
        float4 m0 = *(const float4*)(memory + ga);
        float4 m1 = *(const float4*)(memory + ga + 4);
        float4 p0 = *(const float4*)(pos + ga);
        float4 p1 = *(const float4*)(pos + ga + 4);
        uint4 x;
        x.x = bfp(m0.x + p0.x, m0.y + p0.y);
        x.y = bfp(m0.z + p0.z, m0.w + p0.w);
        x.z = bfp(m1.x + p1.x, m1.y + p1.y);
        x.w = bfp(m1.z + p1.z, m1.w + p1.w);
        *(uint4*)(sh + srow * STRW + (cg >> 1)) = x;
    }
    CPA_WAIT1();
    __syncthreads();    // A staged + W chunk 0 ready

    // ---- preload A fragments (16 rows x 256 k per warp) -> 64 regs -------
    u32 af[64];
    {
        u32 abase = AbB + (wm * 16 + (lane & 15)) * 528 + ((lane >> 4) << 4);
#pragma unroll
        for (int ks = 0; ks < 16; ks++)
            LDSM4(af[ks * 4], af[ks * 4 + 1], af[ks * 4 + 2], af[ks * 4 + 3],
                  abase + ks * 32);
    }

    float ss0 = 0.f, ss1 = 0.f;
    const int r0 = wm * 16 + gid;
    const u32 bgeo = (wj * 16 + (lane & 7) + ((lane >> 4) << 3)) * 528
                   + (((lane >> 3) & 1) << 4);

    // ---- phase 1: kp = A @ Wp^T, eight 32-j chunks, double-buffered ------
#pragma unroll 1
    for (int c = 0; c < 8; c++) {
        if (c > 0) {
            if (c >= 7) { CPA_WAIT0(); } else { CPA_WAIT1(); }
            __syncthreads();
        }
        float ac0[4] = {0.f, 0.f, 0.f, 0.f};
        float ac1[4] = {0.f, 0.f, 0.f, 0.f};
        u32 bbase = WsB + (c & 1) * 16896 + bgeo;
#pragma unroll
        for (int ks = 0; ks < 16; ks++) {
            u32 b0, b1, b2, b3;
            LDSM4(b0, b1, b2, b3, bbase + ks * 32);
            MMA16816(ac0, af[ks*4], af[ks*4+1], af[ks*4+2], af[ks*4+3], b0, b1);
            MMA16816(ac1, af[ks*4], af[ks*4+1], af[ks*4+2], af[ks*4+3], b2, b3);
        }
        // epilogue: +bias, bf16 kp -> Kb, norm partials
        {
            int jg = c * 32 + wj * 16 + tig * 2;
            float b0f = sBias[jg], b1f = sBias[jg + 1];
            float v0 = ac0[0] + b0f, v1 = ac0[1] + b1f;
            float v2 = ac0[2] + b0f, v3 = ac0[3] + b1f;
            Kb[r0 * STRW + (jg >> 1)] = bfp(v0, v1);
            Kb[(r0 + 8) * STRW + (jg >> 1)] = bfp(v2, v3);
            ss0 = fmaf(v0, v0, fmaf(v1, v1, ss0));
            ss1 = fmaf(v2, v2, fmaf(v3, v3, ss1));
            jg += 8;
            b0f = sBias[jg]; b1f = sBias[jg + 1];
            v0 = ac1[0] + b0f; v1 = ac1[1] + b1f;
            v2 = ac1[2] + b0f; v3 = ac1[3] + b1f;
            Kb[r0 * STRW + (jg >> 1)] = bfp(v0, v1);
            Kb[(r0 + 8) * STRW + (jg >> 1)] = bfp(v2, v3);
            ss0 = fmaf(v0, v0, fmaf(v1, v1, ss0));
            ss1 = fmaf(v2, v2, fmaf(v3, v3, ss1));
        }
        __syncthreads();    // all warps done reading Ws[c&1]
        if (c < 6) {
            const u32* src = g_WpB + (c + 2) * 4096;
            u32 dstb = WsB + (c & 1) * 16896;
#pragma unroll
            for (int it = 0; it < 4; it++) {
                int idx = tid + it * 256;
                int row = idx >> 5, c4 = (idx & 31) * 4;
                CPA16(dstb + row * 528 + c4 * 4, src + row * 128 + c4);
            }
            CPA_COMMIT();
        }
    }

    // ---- norms + transition to phase 2 -----------------------------------
    ss0 += __shfl_xor_sync(0xFFFFFFFFu, ss0, 1);
    ss0 += __shfl_xor_sync(0xFFFFFFFFu, ss0, 2);
    ss1 += __shfl_xor_sync(0xFFFFFFFFu, ss1, 1);
    ss1 += __shfl_xor_sync(0xFFFFFFFFu, ss1, 2);
    if (tig == 0) {
        sNorm[r0 * 2 + wj] = ss0;
        sNorm[(r0 + 8) * 2 + wj] = ss1;
    }
    if (tid < 128) sBest[tid] = 0ull;

    // issue Q chunks 0,1
    {
        const u32* qsrc = g_qB + n * 16384;
#pragma unroll
        for (int it = 0; it < 4; it++) {
            int idx = tid + it * 256;
            int row = idx >> 5, c4 = (idx & 31) * 4;
            CPA16(WsB + row * 528 + c4 * 4, qsrc + row * 128 + c4);
        }
        CPA_COMMIT();
#pragma unroll
        for (int it = 0; it < 4; it++) {
            int idx = tid + it * 256;
            int row = idx >> 5, c4 = (idx & 31) * 4;
            CPA16(WsB + 16896 + row * 528 + c4 * 4, qsrc + 4096 + row * 128 + c4);
        }
        CPA_COMMIT();
    }
    __syncthreads();
    if (tid < 64)
        sRsq[tid] = 1.0f / fmaxf(sqrtf(sNorm[tid * 2] + sNorm[tid * 2 + 1]), 1e-12f);
    __syncthreads();

    // ---- preload kp fragments (16 s x 256 k per warp) -> 64 regs ---------
    const int sw = w >> 1, lw = w & 1;      // phase-2 roles (s-group x l-half)
    u32 bf[64];
    {
        u32 kbase = KbB + (sw * 16 + (lane & 7) + ((lane >> 4) << 3)) * 528
                  + (((lane >> 3) & 1) << 4);
#pragma unroll
        for (int ks = 0; ks < 16; ks++)
            LDSM4(bf[ks * 4], bf[ks * 4 + 1], bf[ks * 4 + 2], bf[ks * 4 + 3],
                  kbase + ks * 32);
    }

    const u32 ageo2 = (lw * 16 + (lane & 15)) * 528 + ((lane >> 4) << 4);
    const int sb = sw * 16;

    // ---- phase 2: logits = Q @ kp^T, four 32-l chunks --------------------
#pragma unroll 1
    for (int cc = 0; cc < 4; cc++) {
        if (cc >= 3) { CPA_WAIT0(); } else { CPA_WAIT1(); }
        __syncthreads();
        float ac0[4] = {0.f, 0.f, 0.f, 0.f};
        float ac1[4] = {0.f, 0.f, 0.f, 0.f};
        u32 abase = WsB + (cc & 1) * 16896 + ageo2;
#pragma unroll
        for (int ks = 0; ks < 16; ks++) {
            u32 a0, a1, a2, a3;
            LDSM4(a0, a1, a2, a3, abase + ks * 32);
            MMA16816(ac0, a0, a1, a2, a3, bf[ks * 4], bf[ks * 4 + 1]);
            MMA16816(ac1, a0, a1, a2, a3, bf[ks * 4 + 2], bf[ks * 4 + 3]);
        }
        // scale + per-l argmax (smem atomics)
        float ra = sRsq[sb + tig * 2],     rb2 = sRsq[sb + tig * 2 + 1];
        float rc = sRsq[sb + 8 + tig * 2], rd = sRsq[sb + 8 + tig * 2 + 1];
        float v00 = ac0[0] * ra, v01 = ac0[1] * rb2;
        float v02 = ac1[0] * rc, v03 = ac1[1] * rd;     // l0 values
        float v10 = ac0[2] * ra, v11 = ac0[3] * rb2;
        float v12 = ac1[2] * rc, v13 = ac1[3] * rd;     // l1 values
        int s00 = srow0 + sb + tig * 2;
        int l0 = cc * 32 + lw * 16 + gid, l1 = l0 + 8;

        float bv0 = v00; int bs0 = s00;
        if (v01 > bv0) { bv0 = v01; bs0 = s00 + 1; }
        if (v02 > bv0) { bv0 = v02; bs0 = s00 + 8; }
        if (v03 > bv0) { bv0 = v03; bs0 = s00 + 9; }
        float bv1 = v10; int bs1 = s00;
        if (v11 > bv1) { bv1 = v11; bs1 = s00 + 1; }
        if (v12 > bv1) { bv1 = v12; bs1 = s00 + 8; }
        if (v13 > bv1) { bv1 = v13; bs1 = s00 + 9; }
        ull p0 = ((ull)fkey(bv0) << 32) | (ull)(0xFFFFFFFFu - (u32)bs0);
        ull p1 = ((ull)fkey(bv1) << 32) | (ull)(0xFFFFFFFFu - (u32)bs1);
#pragma unroll
        for (int m = 1; m <= 2; m <<= 1) {
            ull o = __shfl_xor_sync(0xFFFFFFFFu, p0, m); if (o > p0) p0 = o;
            o = __shfl_xor_sync(0xFFFFFFFFu, p1, m); if (o > p1) p1 = o;
        }
        if (tig == 0) {
            atomicMax(&sBest[l0], p0);
            atomicMax(&sBest[l1], p1);
        }
        __syncthreads();
        if (tid < 32) {
            int lg = cc * 32 + tid;
            ull sbv = sBest[lg];
            ull old = atomicMax(&g_bestA[n * L_ + lg], sbv);
            sThr[tid] = fmaxf(unfkey((u32)(sbv >> 32)),
                              unfkey((u32)(old >> 32))) - MARGIN;
        }
        __syncthreads();
        {
            float t0 = sThr[lw * 16 + gid], t1 = sThr[lw * 16 + gid + 8];
#define EMIT(v, s, l, thr) \
            if ((v) >= (thr)) { \
                int ci = atomicAdd(&g_ncand, 1); \
                if (ci < CAND_CAP) \
                    g_cand[ci] = make_uint4((u32)n, (u32)(l), (u32)(s), \
                                            __float_as_uint(v)); \
            }
            EMIT(v00, s00,     l0, t0); EMIT(v01, s00 + 1, l0, t0);
            EMIT(v02, s00 + 8, l0, t0); EMIT(v03, s00 + 9, l0, t0);
            EMIT(v10, s00,     l1, t1); EMIT(v11, s00 + 1, l1, t1);
            EMIT(v12, s00 + 8, l1, t1); EMIT(v13, s00 + 9, l1, t1);
#undef EMIT
        }
        __syncthreads();    // Ws[cc&1] free
        if (cc < 2) {
            const u32* src = g_qB + n * 16384 + (cc + 2) * 4096;
            u32 dstb = WsB + (cc & 1) * 16896;
#pragma unroll
            for (int it = 0; it < 4; it++) {
                int idx = tid + it * 256;
                int row = idx >> 5, c4 = (idx & 31) * 4;
                CPA16(dstb + row * 528 + c4 * 4, src + row * 128 + c4);
            }
            CPA_COMMIT();
        }
    }
}

// ---------------- filter: keep candidates near global approx max ------------
__global__ void __launch_bounds__(256)
filterKernel() {
    int nc = g_ncand; if (nc > CAND_CAP) nc = CAND_CAP;
    for (int i = blockIdx.x * blockDim.x + threadIdx.x; i < nc;
         i += gridDim.x * blockDim.x) {
        uint4 e = g_cand[i];
        float gmax = unfkey((u32)(g_bestA[e.x * L_ + e.y] >> 32));
        if (__uint_as_float(e.w) >= gmax - MARGIN) {
            int si = atomicAdd(&g_nsurv, 1);
            if (si < SURV_CAP) g_surv[si] = e;
        }
    }
}

// ---------------- refine: exact fp32 logits for survivors -------------------
__global__ void __launch_bounds__(256)
refineKernel(const float* __restrict__ memory, const float* __restrict__ pos,
             const float* __restrict__ bp) {
    __shared__ float aS[8 * 260];
    __shared__ float qS[8 * 260];
    __shared__ float red[2][8][8];
    __shared__ uint4 eS[8];
    const int tid = threadIdx.x;
    int nsurv = g_nsurv; if (nsurv > SURV_CAP) nsurv = SURV_CAP;
    int ngroups = (nsurv + 7) >> 3;

    for (int g = blockIdx.x; g < ngroups; g += gridDim.x) {
        if (tid < 8) {
            int i = g * 8 + tid;
            eS[tid] = (i < nsurv) ? g_surv[i] : make_uint4(0, 0, 0xFFFFFFFFu, 0);
        }
        __syncthreads();
#pragma unroll
        for (int r = 0; r < 8; r++) {
            uint4 e = eS[r];
            int s = (e.z == 0xFFFFFFFFu) ? 0 : (int)e.z;
            int ga = (s * N_ + (int)e.x) * C_ + tid;
            aS[r * 260 + tid] = memory[ga] + pos[ga];
            qS[r * 260 + tid] = g_qproj[((int)e.x * L_ + (int)e.y) * C_ + tid];
        }
        __syncthreads();

        const int j = tid;
        float kp[8];
#pragma unroll
        for (int r = 0; r < 8; r++) kp[r] = bp[j];
#pragma unroll 4
        for (int c = 0; c < C_; c++) {
            float wv = g_WpT[c * C_ + j];
#pragma unroll
            for (int r = 0; r < 8; r++) kp[r] = fmaf(aS[r * 260 + c], wv, kp[r]);
        }
        const int lane = tid & 31, wrp = tid >> 5;
#pragma unroll
        for (int r = 0; r < 8; r++) {
            float v2 = kp[r] * kp[r];
            float vq = kp[r] * qS[r * 260 + j];
#pragma unroll
            for (int m = 16; m >= 1; m >>= 1) {
                v2 += __shfl_xor_sync(0xFFFFFFFFu, v2, m);
                vq += __shfl_xor_sync(0xFFFFFFFFu, vq, m);
            }
            if (lane == 0) { red[0][r][wrp] = v2; red[1][r][wrp] = vq; }
        }
        __syncthreads();
        if (tid < 8) {
            const int r = tid;
            float ss = 0.f, qq = 0.f;
#pragma unroll
            for (int ww = 0; ww < 8; ww++) { ss += red[0][r][ww]; qq += red[1][r][ww]; }
            uint4 e = eS[r];
            if (e.z != 0xFFFFFFFFu) {
                float rsq = 1.0f / fmaxf(sqrtf(ss), 1e-12f);
                float logit = qq * rsq;
                atomicMax(&g_bestE[e.x * L_ + e.y],
                          ((ull)fkey(logit) << 32) | (ull)(0xFFFFFFFFu - e.z));
            }
        }
        __syncthreads();
    }
}

// ---------------- epilogue: winners -> v -> upd -> residual + LN ------------
__device__ __forceinline__ void gemvT(const float* inb, float* outb,
                                      const float* __restrict__ WT,
                                      const float* __restrict__ bias, int j) {
    float acc[8];
#pragma unroll
    for (int r = 0; r < 8; r++) acc[r] = bias[j];
#pragma unroll 4
    for (int c = 0; c < C_; c++) {
        float wv = WT[c * C_ + j];
#pragma unroll
        for (int r = 0; r < 8; r++) acc[r] = fmaf(inb[r * 260 + c], wv, acc[r]);
    }
#pragma unroll
    for (int r = 0; r < 8; r++) outb[r * 260 + j] = acc[r];
}

__global__ void __launch_bounds__(256)
finalKernel(const float* __restrict__ tgt, const float* __restrict__ memory,
            const float* __restrict__ pos,
            const float* __restrict__ bp, const float* __restrict__ bv,
            const float* __restrict__ bo,
            const float* __restrict__ gamma, const float* __restrict__ beta,
            float* __restrict__ out) {
    __shared__ float bufX[8 * 260];
    __shared__ float bufY[8 * 260];
    __shared__ unsigned sidx[8];
    const int tid = threadIdx.x;
    const int b = blockIdx.x;
    const int n = b >> 4;

    if (tid < 8) {
        ull pk = g_bestE[b * 8 + tid];
        sidx[tid] = 0xFFFFFFFFu - (unsigned)(pk & 0xFFFFFFFFu);
    }
    __syncthreads();

    for (int idx = tid; idx < 8 * 256; idx += 256) {
        int r = idx >> 8, j = idx & 255;
        int s = (int)sidx[r];
        int g = (s * N_ + n) * C_ + j;
        bufX[r * 260 + j] = memory[g] + pos[g];
    }
    __syncthreads();
    gemvT(bufX, bufY, g_WpT, bp, tid);  __syncthreads();
    gemvT(bufY, bufX, g_WvT, bv, tid);  __syncthreads();
    gemvT(bufX, bufY, g_WoT, bo, tid);  __syncthreads();

#pragma unroll
    for (int r = 0; r < 8; r++) {
        int l = (b & 15) * 8 + r;
        bufY[r * 260 + tid] += tgt[(l * N_ + n) * C_ + tid];
    }
    __syncthreads();

    const int w = tid >> 5, lane = tid & 31;
    float s1 = 0.f, s2 = 0.f;
#pragma unroll
    for (int k = 0; k < 8; k++) {
        float v = bufY[w * 260 + lane + k * 32];
        s1 += v;
        s2 = fmaf(v, v, s2);
    }
#pragma unroll
    for (int m = 16; m >= 1; m >>= 1) {
        s1 += __shfl_xor_sync(0xFFFFFFFFu, s1, m);
        s2 += __shfl_xor_sync(0xFFFFFFFFu, s2, m);
    }
    float mu = s1 * (1.0f / 256.0f);
    float var = s2 * (1.0f / 256.0f) - mu * mu;
    float rstd = rsqrtf(var + 1e-5f);

    int l = (b & 15) * 8 + w;
    float* o = out + (l * N_ + n) * C_;
#pragma unroll
    for (int k = 0; k < 8; k++) {
        int j = lane + k * 32;
        float v = bufY[w * 260 + j];
        o[j] = (v - mu) * rstd * gamma[j] + beta[j];
    }
}

// ============================================================================
extern "C" void kernel_launch(void* const* d_in, const int* in_sizes, int n_in,
                              void* d_out, int out_size) {
    const float* tgt    = (const float*)d_in[0];
    const float* memory = (const float*)d_in[1];
    const float* pos    = (const float*)d_in[2];
    const float* qpos   = (const float*)d_in[3];
    const float* Wq     = (const float*)d_in[4];
    const float* bq     = (const float*)d_in[5];
    const float* Wp     = (const float*)d_in[6];
    const float* bp     = (const float*)d_in[7];
    const float* Wv     = (const float*)d_in[8];
    const float* bv     = (const float*)d_in[9];
    const float* Wo     = (const float*)d_in[10];
    const float* bo     = (const float*)d_in[11];
    const float* gamma  = (const float*)d_in[12];
    const float* beta   = (const float*)d_in[13];
    float* out = (float*)d_out;

    cudaFuncSetAttribute(fusedMMA, cudaFuncAttributeMaxDynamicSharedMemorySize,
                         SMEM_BYTES);

    convWKernel<<<256, 256>>>(Wp, Wv, Wo);
    qprojKernel<<<64, 256>>>(tgt, qpos, Wq, bq);
    fusedMMA<<<dim3(S_ / 64, N_), 256, SMEM_BYTES>>>(memory, pos, bp);
    filterKernel<<<128, 256>>>();
    refineKernel<<<128, 256>>>(memory, pos, bp);
    finalKernel<<<128, 256>>>(tgt, memory, pos, bp, bv, bo, gamma, beta, out);
}